// round 6
// baseline (speedup 1.0000x reference)
#include <cuda_runtime.h>
#include <cstdint>
#include <cfloat>

#define DIMD 64
#define NCODE 512
#define HW 4096
#define TPB 256
#define GRID 148
#define NVEC 131072
#define TILEV 256                  // vectors per block-tile
#define NTILES (NVEC / TILEV)      // 512
#define CAP 4
#define MARGIN 1.5e-3f

// smem byte offsets
#define BP_OFF   0        // float2[64 nsub][8 s][32 lane] exact W in frag order (128KB)
#define XS_OFF   131072   // float[256][65] X tile (66560B)
#define WN_OFF   197632   // ||w||^2 [512]
#define WI_OFF   199680   // 1 - ||w||^2/2 [512]
#define CODE_OFF 201728   // int[256] winning code per vec (reused as loss scratch)
#define A2_OFF   202752   // float[256] ||x||^2 per vec
#define SMEM_TOTAL 203776

__device__ float g_psum[GRID];

extern __shared__ char smc[];

// fetch exact W[code][d] from the fragment-ordered smem copy
__device__ __forceinline__ float wfetch(const float2* bp, int code, int d) {
    float2 v = bp[(((code >> 3) << 3) + (d >> 3)) * 32 + ((code & 7) << 2) + (d & 3)];
    return ((d >> 2) & 1) ? v.y : v.x;
}

// Bitwise-identical arithmetic to the R3 kernel (rel_err == 0.0)
__device__ __forceinline__ float exact_dist(const float* xr, float A,
                                            const float2* bp,
                                            const float* wn_s, int code) {
    float s0 = 0.f, s1 = 0.f, s2 = 0.f, s3 = 0.f;
#pragma unroll
    for (int i = 0; i < 16; i++) {
        s0 = fmaf(xr[4*i+0], wfetch(bp, code, 4*i+0), s0);
        s1 = fmaf(xr[4*i+1], wfetch(bp, code, 4*i+1), s1);
        s2 = fmaf(xr[4*i+2], wfetch(bp, code, 4*i+2), s2);
        s3 = fmaf(xr[4*i+3], wfetch(bp, code, 4*i+3), s3);
    }
    float Bv = (s0 + s1) + (s2 + s3);
    return fmaf(-2.f, Bv, A) + wn_s[code];
}

__global__ void __launch_bounds__(TPB, 1)
vq_mma_kernel(const float* __restrict__ in, const float* __restrict__ w,
              float* __restrict__ out_disc, float* __restrict__ out_q)
{
    const int tid = threadIdx.x, bid = blockIdx.x;
    const int wid = tid >> 5, lane = tid & 31;
    const int g = lane >> 2, q = lane & 3;

    float2* bp     = (float2*)(smc + BP_OFF);
    float*  xs     = (float*)(smc + XS_OFF);
    float*  wn_s   = (float*)(smc + WN_OFF);
    float*  wi_s   = (float*)(smc + WI_OFF);
    int*    code_s = (int*)(smc + CODE_OFF);
    float*  a2_s   = (float*)(smc + A2_OFF);

    // ---- prologue: codebook -> fragment-ordered smem (exact fp32), norms ----
    for (int idx = tid; idx < 64 * 8 * 32; idx += TPB) {
        int nsub = idx >> 8, rem = idx & 255, s = rem >> 5, l2 = rem & 31;
        int n = nsub * 8 + (l2 >> 2), k = s * 8 + (l2 & 3);
        bp[idx] = make_float2(w[n * 64 + k], w[n * 64 + k + 4]);
    }
    for (int c = tid; c < NCODE; c += TPB) {
        const float* row = w + c * 64;
        float s = 0.f;
#pragma unroll
        for (int d = 0; d < 64; d++) s = fmaf(row[d], row[d], s);
        wn_s[c] = s;
        wi_s[c] = 1.0f - 0.5f * s;   // accumulator init: key bias +1, -wn/2 folded
    }
    __syncthreads();

    const int vbase = wid * 32;      // 32 vectors per warp
    float lsum = 0.f;

    for (int tile = bid; tile < NTILES; tile += GRID) {
        const int vb = tile * TILEV;
        const int b = vb >> 12, hw0 = vb & (HW - 1);
        const float* gx = in + ((size_t)b << 18) + hw0;

        // stage X tile: xs[v][d] = in[b][d][hw0+v]  (coalesced reads)
        for (int idx = tid; idx < TILEV * 64; idx += TPB) {
            int d = idx >> 8, v = idx & 255;
            xs[v * 65 + d] = gx[((size_t)d << 12) + v];
        }
        __syncthreads();
        {   // per-row ||x||^2, sequential d (same order as exact path)
            float A = 0.f;
            const float* xr = xs + tid * 65;
#pragma unroll
            for (int d = 0; d < 64; d++) { float t = xr[d]; A = fmaf(t, t, A); }
            a2_s[tid] = A;
        }
        __syncthreads();

        // A fragments (raw fp32 bits; tf32 MMA truncates)
        uint32_t afr[2][8][4];
#pragma unroll
        for (int t = 0; t < 2; t++)
#pragma unroll
            for (int s = 0; s < 8; s++) {
                int r0 = vbase + t * 16 + g, k0 = s * 8 + q;
                afr[t][s][0] = __float_as_uint(xs[r0 * 65 + k0]);
                afr[t][s][1] = __float_as_uint(xs[(r0 + 8) * 65 + k0]);
                afr[t][s][2] = __float_as_uint(xs[r0 * 65 + k0 + 4]);
                afr[t][s][3] = __float_as_uint(xs[(r0 + 8) * 65 + k0 + 4]);
            }

        float rmaxf[4], thr[4], candf[4][CAP];
        int cnt[4], ovf = 0;
#pragma unroll
        for (int r = 0; r < 4; r++) {
            rmaxf[r] = -FLT_MAX; thr[r] = -FLT_MAX; cnt[r] = 0;
#pragma unroll
            for (int sl = 0; sl < CAP; sl++) candf[r][sl] = -FLT_MAX;
        }

#pragma unroll 1
        for (int nsub = 0; nsub < 64; nsub++) {
            const int cbase = nsub * 8;
            uint32_t bfr[8][2];
            const float2* bpn = bp + nsub * 256;
#pragma unroll
            for (int s = 0; s < 8; s++) {
                float2 v = bpn[s * 32 + lane];
                bfr[s][0] = __float_as_uint(v.x);
                bfr[s][1] = __float_as_uint(v.y);
            }
            float2 wi = *(const float2*)(wi_s + cbase + 2 * q);
            float dd[2][4];
#pragma unroll
            for (int t = 0; t < 2; t++) {
                dd[t][0] = wi.x; dd[t][1] = wi.y; dd[t][2] = wi.x; dd[t][3] = wi.y;
            }
#pragma unroll
            for (int s = 0; s < 8; s++)
#pragma unroll
                for (int t = 0; t < 2; t++)
                    asm volatile(
                        "mma.sync.aligned.m16n8k8.row.col.f32.tf32.tf32.f32 "
                        "{%0,%1,%2,%3}, {%4,%5,%6,%7}, {%8,%9}, {%0,%1,%2,%3};"
                        : "+f"(dd[t][0]), "+f"(dd[t][1]), "+f"(dd[t][2]), "+f"(dd[t][3])
                        : "r"(afr[t][s][0]), "r"(afr[t][s][1]),
                          "r"(afr[t][s][2]), "r"(afr[t][s][3]),
                          "r"(bfr[s][0]), "r"(bfr[s][1]));

            // scan 8 keys (key = 1 + x.w - wn/2; argmax == argmin dist)
#pragma unroll
            for (int t = 0; t < 2; t++)
#pragma unroll
                for (int j = 0; j < 4; j++) {
                    const int rid = t * 2 + (j >> 1);
                    float kb = dd[t][j];
                    if (kb > thr[rid]) {          // rare slow path
                        int code = cbase + 2 * q + (j & 1);
                        float uf = __uint_as_float(
                            (__float_as_uint(kb) & ~511u) | (uint32_t)code);
                        if (uf > rmaxf[rid]) { rmaxf[rid] = uf; thr[rid] = uf - MARGIN; }
                        if (cnt[rid] >= CAP) {    // purge dead entries
                            float th2 = thr[rid];
                            float v0 = candf[rid][0], v1 = candf[rid][1];
                            float v2 = candf[rid][2], v3 = candf[rid][3];
                            int nc = 0;
                            float w0 = -FLT_MAX, w1 = -FLT_MAX, w2 = -FLT_MAX, w3 = -FLT_MAX;
                            if (v0 > th2) { w0 = v0; nc = 1; }
                            if (v1 > th2) { if (nc == 0) w0 = v1; else w1 = v1; nc++; }
                            if (v2 > th2) { if (nc == 0) w0 = v2; else if (nc == 1) w1 = v2; else w2 = v2; nc++; }
                            if (v3 > th2) { if (nc == 0) w0 = v3; else if (nc == 1) w1 = v3; else if (nc == 2) w2 = v3; else w3 = v3; nc++; }
                            candf[rid][0] = w0; candf[rid][1] = w1;
                            candf[rid][2] = w2; candf[rid][3] = w3;
                            cnt[rid] = nc;
                        }
                        if (cnt[rid] < CAP) {
#pragma unroll
                            for (int sl = 0; sl < CAP; sl++)
                                if (sl == cnt[rid]) candf[rid][sl] = uf;
                            cnt[rid]++;
                        } else ovf |= 1 << rid;   // sticky -> exact rescan
                    }
                }
        }

        // ---- rescore + quad reduce + write codes ----
#pragma unroll
        for (int rid = 0; rid < 4; rid++) {
            float gm = rmaxf[rid];
            gm = fmaxf(gm, __shfl_xor_sync(0xffffffffu, gm, 1));
            gm = fmaxf(gm, __shfl_xor_sync(0xffffffffu, gm, 2));
            const float fthr = gm - MARGIN;
            const int row = vbase + ((rid & 1) << 3) + ((rid >> 1) << 4) + g;
            const float A = a2_s[row];
            const float* xr = xs + row * 65;
            float bd = FLT_MAX; int bic = 1023;
            if (ovf & (1 << rid)) {               // exact rescan of this thread's 128 codes
                for (int c8 = 0; c8 < 64; c8++)
#pragma unroll
                    for (int b2 = 0; b2 < 2; b2++) {
                        int code = c8 * 8 + 2 * q + b2;
                        float dv = exact_dist(xr, A, bp, wn_s, code);
                        if (dv < bd) { bd = dv; bic = code; }
                    }
            } else {
#pragma unroll
                for (int sl = 0; sl < CAP; sl++)
                    if (sl < cnt[rid] && candf[rid][sl] > fthr) {
                        int code = (int)(__float_as_uint(candf[rid][sl]) & 511u);
                        float dv = exact_dist(xr, A, bp, wn_s, code);
                        if (dv < bd) { bd = dv; bic = code; }  // ascending codes: first-min
                    }
            }
            unsigned long long key =
                ((unsigned long long)__float_as_uint(bd) << 32) | (unsigned)bic;
            unsigned long long o1 = __shfl_xor_sync(0xffffffffu, key, 1);
            key = o1 < key ? o1 : key;
            unsigned long long o2 = __shfl_xor_sync(0xffffffffu, key, 2);
            key = o2 < key ? o2 : key;
            if (q == 0) {
                int code = (int)(key & 1023u);
                code_s[row] = code;
                out_disc[vb + row] = (float)code;
            }
        }
        __syncthreads();

        // ---- epilogue: quantized (fl(x + fl(w-x))) + loss, coalesced over hw ----
        for (int idx = tid; idx < TILEV * 64; idx += TPB) {
            int d = idx >> 8, v = idx & 255;
            int code = code_s[v];
            float x = xs[v * 65 + d];
            float diff = wfetch(bp, code, d) - x;
            out_q[((size_t)b << 18) + ((size_t)d << 12) + hw0 + v] = x + diff;
            lsum = fmaf(diff, diff, lsum);
        }
        __syncthreads();
    }

    // ---- deterministic loss reduction ----
    float* red = (float*)(smc + CODE_OFF);
    red[tid] = lsum;
    __syncthreads();
#pragma unroll
    for (int s = TPB / 2; s > 0; s >>= 1) {
        if (tid < s) red[tid] += red[tid + s];
        __syncthreads();
    }
    if (tid == 0) g_psum[bid] = red[0];
}

__global__ void vq_final_kernel(float* __restrict__ out_loss, float inv_total) {
    if (threadIdx.x == 0 && blockIdx.x == 0) {
        float s = 0.f;
        for (int i = 0; i < GRID; i++) s += g_psum[i];
        float m = s * inv_total;
        out_loss[0] = m + 0.25f * m;
    }
}

extern "C" void kernel_launch(void* const* d_in, const int* in_sizes, int n_in,
                              void* d_out, int out_size)
{
    const float* in = (const float*)d_in[0];   // [32,64,64,64] fp32
    const float* w  = (const float*)d_in[1];   // [512,64] fp32
    const int n_elems = in_sizes[0];           // 8388608
    const int nvec    = n_elems / DIMD;        // 131072

    float* out      = (float*)d_out;
    float* out_disc = out;
    float* out_q    = out + nvec;
    float* out_loss = out + nvec + n_elems;

    static bool attr_set = false;
    if (!attr_set) {
        cudaFuncSetAttribute(vq_mma_kernel,
                             cudaFuncAttributeMaxDynamicSharedMemorySize, SMEM_TOTAL);
        attr_set = true;
    }
    vq_mma_kernel<<<GRID, TPB, SMEM_TOTAL>>>(in, w, out_disc, out_q);
    vq_final_kernel<<<1, 32>>>(out_loss, 1.0f / (float)n_elems);
}

// round 7
// speedup vs baseline: 3.4092x; 3.4092x over previous
#include <cuda_runtime.h>
#include <cstdint>
#include <cfloat>
#include <climits>

#define DIMD 64
#define NCODE 512
#define HW 4096
#define TPB 512
#define GRID 148
#define NVEC 131072
#define NUNITS (NVEC / 32)          // 4096 warp-units (32 vectors each)
#define USTRIDE (GRID * (TPB / 32)) // 2368
#define CAP 16

// smem byte offsets
#define QW_OFF 0          // int8 codebook [513][64] (one zero pad row)
#define WN_OFF 33024      // ||w||^2 [512]
#define RED_OFF 35072     // reduce scratch [512]
#define WP_OFF 37120      // fp32 codebook, padded rows of 68 floats (139264B)
#define SMEM_TOTAL 176384

__device__ float g_psum[GRID];

extern __shared__ char smc[];

// Bitwise-identical to the R3 kernel (rel_err == 0.0): 4 fmaf chains,
// Bv = (s0+s1)+(s2+s3), dist = fl(A - 2B) + wn.
__device__ __forceinline__ float exact_dist(const float* xv, float A,
                                            const float* wp,
                                            const float* wn_s, int code) {
    const float4* wr = (const float4*)(wp + code * 68);
    float s0 = 0.f, s1 = 0.f, s2 = 0.f, s3 = 0.f;
#pragma unroll
    for (int i = 0; i < 16; i++) {
        float4 wv = wr[i];
        s0 = fmaf(xv[4*i+0], wv.x, s0);
        s1 = fmaf(xv[4*i+1], wv.y, s1);
        s2 = fmaf(xv[4*i+2], wv.z, s2);
        s3 = fmaf(xv[4*i+3], wv.w, s3);
    }
    float Bv = (s0 + s1) + (s2 + s3);
    return fmaf(-2.f, Bv, A) + wn_s[code];
}

__global__ void __launch_bounds__(TPB, 1)
vq_dp4a_kernel(const float* __restrict__ in, const float* __restrict__ w,
               float* __restrict__ out_disc, float* __restrict__ out_q)
{
    const int tid = threadIdx.x, bid = blockIdx.x;
    const int wid = tid >> 5, lane = tid & 31;
    char*  qw   = smc + QW_OFF;
    float* wn_s = (float*)(smc + WN_OFF);
    float* red  = (float*)(smc + RED_OFF);
    float* wp   = (float*)(smc + WP_OFF);
    int*   redi = (int*)red;

    // ================= prologue =================
    // global |w| max
    float lm = 0.f;
    for (int i = tid; i < NCODE * DIMD; i += TPB) lm = fmaxf(lm, fabsf(w[i]));
    red[tid] = lm; __syncthreads();
#pragma unroll
    for (int s = TPB/2; s > 0; s >>= 1) {
        if (tid < s) red[tid] = fmaxf(red[tid], red[tid + s]);
        __syncthreads();
    }
    const float wmax = red[0];
    __syncthreads();

    // per-code (tid == code): copy fp32 row, wn, int8 quantize, sum|q|
    float wn_mine; int sabs_mine;
    {
        const float inv_w = 127.0f / wmax;
        const float4* src = (const float4*)(w + tid * DIMD);
        float4* dst = (float4*)(wp + tid * 68);
        int4* qrow = (int4*)(qw + tid * 64);
        float s = 0.f; int sabs = 0;
#pragma unroll
        for (int i = 0; i < 16; i += 4) {
            int pk[4];
#pragma unroll
            for (int j = 0; j < 4; j++) {
                float4 v = src[i + j];
                dst[i + j] = v;
                s = fmaf(v.x, v.x, s); s = fmaf(v.y, v.y, s);
                s = fmaf(v.z, v.z, s); s = fmaf(v.w, v.w, s);
                int q0 = __float2int_rn(v.x * inv_w);
                int q1 = __float2int_rn(v.y * inv_w);
                int q2 = __float2int_rn(v.z * inv_w);
                int q3 = __float2int_rn(v.w * inv_w);
                sabs += abs(q0) + abs(q1) + abs(q2) + abs(q3);
                pk[j] = (q0 & 0xff) | ((q1 & 0xff) << 8)
                      | ((q2 & 0xff) << 16) | (q3 << 24);
            }
            qrow[i >> 2] = make_int4(pk[0], pk[1], pk[2], pk[3]);
        }
        wn_s[tid] = s; wn_mine = s; sabs_mine = sabs;
        if (tid < 4) ((int4*)(qw + NCODE * 64))[tid] = make_int4(0,0,0,0); // pad row
    }
    __syncthreads();
    // W1max (int), wnmin, wnmax
    redi[tid] = sabs_mine; __syncthreads();
#pragma unroll
    for (int s = TPB/2; s > 0; s >>= 1) {
        if (tid < s) redi[tid] = max(redi[tid], redi[tid + s]);
        __syncthreads();
    }
    const int W1max = redi[0]; __syncthreads();
    red[tid] = wn_mine; __syncthreads();
#pragma unroll
    for (int s = TPB/2; s > 0; s >>= 1) {
        if (tid < s) red[tid] = fminf(red[tid], red[tid + s]);
        __syncthreads();
    }
    const float wnmin = red[0]; __syncthreads();
    red[tid] = wn_mine; __syncthreads();
#pragma unroll
    for (int s = TPB/2; s > 0; s >>= 1) {
        if (tid < s) red[tid] = fmaxf(red[tid], red[tid + s]);
        __syncthreads();
    }
    const float wn_range = red[0] - wnmin;
    __syncthreads();

    // ================= main per-warp unit loop =================
    float lsum = 0.f;
    const float sw = wmax * (1.0f / 127.0f);

    for (int u = bid + wid * GRID; u < NUNITS; u += USTRIDE) {
        const int vec = u * 32 + lane;
        const int b = vec >> 12, hw = vec & (HW - 1);
        const float* xb = in + ((size_t)b << 18) + hw;

        // ---- load x, stats, quantize (xv scoped: dead during scan) ----
        float sxmax = 0.f, X1 = 0.f, A = 0.f;
        int qx[16];
        {
            float xv[DIMD];
#pragma unroll
            for (int d = 0; d < DIMD; d++) {
                float t = xb[(size_t)d << 12];
                xv[d] = t;
                sxmax = fmaxf(sxmax, fabsf(t));
                X1 += fabsf(t);
                A = fmaf(t, t, A);
            }
            float inv_x = (sxmax > 0.f) ? 127.0f / sxmax : 0.f;
#pragma unroll
            for (int i = 0; i < 16; i++) {
                int q0 = __float2int_rn(xv[4*i+0] * inv_x);
                int q1 = __float2int_rn(xv[4*i+1] * inv_x);
                int q2 = __float2int_rn(xv[4*i+2] * inv_x);
                int q3 = __float2int_rn(xv[4*i+3] * inv_x);
                qx[i] = (q0 & 0xff) | ((q1 & 0xff) << 8)
                      | ((q2 & 0xff) << 16) | (q3 << 24);
            }
        }
        // rigorous integer margin
        int M;
        {
            const float sx = sxmax * (1.0f / 127.0f);
            float ssprod = sx * sw;
            float mf = (sxmax > 0.f)
                ? 1.05f * ((float)W1max + 64.0f + X1 * 127.0f / sxmax)
                  + 0.525f * wn_range / ssprod
                : 2.1e9f;
            mf = fminf(mf, 2.1e9f);
            M = (int)ceilf(mf) + 2;
        }

        // ---- int8 scan over 512 codes ----
        int smax = INT_MIN / 2, thr = INT_MIN / 2;
        int cnt = 0, ovf = 0;
        int candC[CAP], candS[CAP];
        const int4* qr = (const int4*)qw;
#pragma unroll 2
        for (int code = 0; code < NCODE; code++) {
            int4 v0 = qr[code*4+0], v1 = qr[code*4+1];
            int4 v2 = qr[code*4+2], v3 = qr[code*4+3];
            int a0 = __dp4a(v0.x, qx[0], 0);
            int a1 = __dp4a(v0.y, qx[1], 0);
            a0 = __dp4a(v0.z, qx[2], a0);  a1 = __dp4a(v0.w, qx[3], a1);
            a0 = __dp4a(v1.x, qx[4], a0);  a1 = __dp4a(v1.y, qx[5], a1);
            a0 = __dp4a(v1.z, qx[6], a0);  a1 = __dp4a(v1.w, qx[7], a1);
            a0 = __dp4a(v2.x, qx[8], a0);  a1 = __dp4a(v2.y, qx[9], a1);
            a0 = __dp4a(v2.z, qx[10], a0); a1 = __dp4a(v2.w, qx[11], a1);
            a0 = __dp4a(v3.x, qx[12], a0); a1 = __dp4a(v3.y, qx[13], a1);
            a0 = __dp4a(v3.z, qx[14], a0); a1 = __dp4a(v3.w, qx[15], a1);
            int s = a0 + a1;
            if (s > thr) {                       // rare path
                if (s > smax) { smax = s; thr = smax - M; }
                if (cnt == CAP) {                // purge entries below threshold
                    int nc = 0;
#pragma unroll
                    for (int sl = 0; sl < CAP; sl++)
                        if (candS[sl] > thr) { candS[nc] = candS[sl]; candC[nc] = candC[sl]; nc++; }
                    cnt = nc;
                }
                if (cnt < CAP) { candS[cnt] = s; candC[cnt] = code; cnt++; }
                else ovf = 1;                    // sticky -> exact full rescan
            }
        }

        // ---- exact rescore (R3-identical arithmetic) ----
        float xv[DIMD];
#pragma unroll
        for (int d = 0; d < DIMD; d++) xv[d] = xb[(size_t)d << 12];

        float bd = FLT_MAX; int bi = 0;
        if (ovf) {
            for (int code = 0; code < NCODE; code++) {
                float dv = exact_dist(xv, A, wp, wn_s, code);
                if (dv < bd) { bd = dv; bi = code; }
            }
        } else {
            const int fthr = smax - M;
            for (int e = 0; e < cnt; e++) {      // ascending codes: first-min ties
                if (candS[e] >= fthr) {
                    float dv = exact_dist(xv, A, wp, wn_s, candC[e]);
                    if (dv < bd) { bd = dv; bi = candC[e]; }
                }
            }
        }

        // ---- epilogue ----
        out_disc[vec] = (float)bi;
        const float4* wb = (const float4*)(wp + bi * 68);
        float* qb = out_q + ((size_t)b << 18) + hw;
#pragma unroll
        for (int i = 0; i < 16; i++) {
            float4 wv = wb[i];
            float d0 = wv.x - xv[4*i+0];
            float d1 = wv.y - xv[4*i+1];
            float d2 = wv.z - xv[4*i+2];
            float d3 = wv.w - xv[4*i+3];
            qb[(size_t)(4*i+0) << 12] = xv[4*i+0] + d0;
            qb[(size_t)(4*i+1) << 12] = xv[4*i+1] + d1;
            qb[(size_t)(4*i+2) << 12] = xv[4*i+2] + d2;
            qb[(size_t)(4*i+3) << 12] = xv[4*i+3] + d3;
            lsum = fmaf(d0, d0, lsum); lsum = fmaf(d1, d1, lsum);
            lsum = fmaf(d2, d2, lsum); lsum = fmaf(d3, d3, lsum);
        }
    }

    // ---- deterministic loss reduction ----
    __syncthreads();
    red[tid] = lsum; __syncthreads();
#pragma unroll
    for (int s = TPB/2; s > 0; s >>= 1) {
        if (tid < s) red[tid] += red[tid + s];
        __syncthreads();
    }
    if (tid == 0) g_psum[bid] = red[0];
}

__global__ void vq_final_kernel(float* __restrict__ out_loss, float inv_total) {
    if (threadIdx.x == 0 && blockIdx.x == 0) {
        float s = 0.f;
        for (int i = 0; i < GRID; i++) s += g_psum[i];
        float m = s * inv_total;
        out_loss[0] = m + 0.25f * m;
    }
}

extern "C" void kernel_launch(void* const* d_in, const int* in_sizes, int n_in,
                              void* d_out, int out_size)
{
    const float* in = (const float*)d_in[0];   // [32,64,64,64] fp32
    const float* w  = (const float*)d_in[1];   // [512,64] fp32
    const int n_elems = in_sizes[0];           // 8388608
    const int nvec    = n_elems / DIMD;        // 131072

    float* out      = (float*)d_out;
    float* out_disc = out;
    float* out_q    = out + nvec;
    float* out_loss = out + nvec + n_elems;

    static bool attr_set = false;
    if (!attr_set) {
        cudaFuncSetAttribute(vq_dp4a_kernel,
                             cudaFuncAttributeMaxDynamicSharedMemorySize, SMEM_TOTAL);
        attr_set = true;
    }
    vq_dp4a_kernel<<<GRID, TPB, SMEM_TOTAL>>>(in, w, out_disc, out_q);
    vq_final_kernel<<<1, 32>>>(out_loss, 1.0f / (float)n_elems);
}

// round 8
// speedup vs baseline: 3.5796x; 1.0500x over previous
#include <cuda_runtime.h>
#include <cstdint>
#include <cfloat>
#include <climits>

#define DIMD 64
#define NCODE 512
#define HW 4096
#define TPB 512
#define GRID 148
#define NVEC 131072
#define NUNITS (NVEC / 32)          // 4096 warp-units (32 vectors each)
#define USTRIDE (GRID * (TPB / 32)) // 2368
#define CAP 16

// smem byte offsets
#define QW_OFF 0          // int8 codebook [513][64] (one zero pad row)
#define WN_OFF 33024      // ||w||^2 [512]
#define RED_OFF 35072     // reduce scratch [512]
#define WP_OFF 37120      // fp32 codebook, padded rows of 68 floats (139264B)
#define SMEM_TOTAL 176384

__device__ float g_psum[GRID];
__device__ int   g_ctr = 0;          // last-block counter (returns to 0 each run)

extern __shared__ char smc[];

// Bitwise-identical to the R3 kernel (rel_err == 0.0): 4 fmaf chains,
// Bv = (s0+s1)+(s2+s3), dist = fl(A - 2B) + wn.
__device__ __forceinline__ float exact_dist(const float* xv, float A,
                                            const float* wp,
                                            const float* wn_s, int code) {
    const float4* wr = (const float4*)(wp + code * 68);
    float s0 = 0.f, s1 = 0.f, s2 = 0.f, s3 = 0.f;
#pragma unroll
    for (int i = 0; i < 16; i++) {
        float4 wv = wr[i];
        s0 = fmaf(xv[4*i+0], wv.x, s0);
        s1 = fmaf(xv[4*i+1], wv.y, s1);
        s2 = fmaf(xv[4*i+2], wv.z, s2);
        s3 = fmaf(xv[4*i+3], wv.w, s3);
    }
    float Bv = (s0 + s1) + (s2 + s3);
    return fmaf(-2.f, Bv, A) + wn_s[code];
}

__global__ void __launch_bounds__(TPB, 1)
vq_dp4a_kernel(const float* __restrict__ in, const float* __restrict__ w,
               float* __restrict__ out_disc, float* __restrict__ out_q,
               float* __restrict__ out_loss, float inv_total)
{
    const int tid = threadIdx.x, bid = blockIdx.x;
    const int lane = tid & 31;
    char*  qw   = smc + QW_OFF;
    float* wn_s = (float*)(smc + WN_OFF);
    float* red  = (float*)(smc + RED_OFF);
    float* wp   = (float*)(smc + WP_OFF);
    int*   redi = (int*)red;

    // ================= prologue =================
    float lm = 0.f;
    for (int i = tid; i < NCODE * DIMD; i += TPB) lm = fmaxf(lm, fabsf(w[i]));
    red[tid] = lm; __syncthreads();
#pragma unroll
    for (int s = TPB/2; s > 0; s >>= 1) {
        if (tid < s) red[tid] = fmaxf(red[tid], red[tid + s]);
        __syncthreads();
    }
    const float wmax = red[0];
    __syncthreads();

    // per-code (tid == code): copy fp32 row, wn, int8 quantize, sum|q|
    float wn_mine; int sabs_mine;
    {
        const float inv_w = 127.0f / wmax;
        const float4* src = (const float4*)(w + tid * DIMD);
        float4* dst = (float4*)(wp + tid * 68);
        int4* qrow = (int4*)(qw + tid * 64);
        float s = 0.f; int sabs = 0;
#pragma unroll
        for (int i = 0; i < 16; i += 4) {
            int pk[4];
#pragma unroll
            for (int j = 0; j < 4; j++) {
                float4 v = src[i + j];
                dst[i + j] = v;
                s = fmaf(v.x, v.x, s); s = fmaf(v.y, v.y, s);
                s = fmaf(v.z, v.z, s); s = fmaf(v.w, v.w, s);
                int q0 = __float2int_rn(v.x * inv_w);
                int q1 = __float2int_rn(v.y * inv_w);
                int q2 = __float2int_rn(v.z * inv_w);
                int q3 = __float2int_rn(v.w * inv_w);
                sabs += abs(q0) + abs(q1) + abs(q2) + abs(q3);
                pk[j] = (q0 & 0xff) | ((q1 & 0xff) << 8)
                      | ((q2 & 0xff) << 16) | (q3 << 24);
            }
            qrow[i >> 2] = make_int4(pk[0], pk[1], pk[2], pk[3]);
        }
        wn_s[tid] = s; wn_mine = s; sabs_mine = sabs;
        if (tid < 4) ((int4*)(qw + NCODE * 64))[tid] = make_int4(0,0,0,0);
    }
    __syncthreads();
    redi[tid] = sabs_mine; __syncthreads();
#pragma unroll
    for (int s = TPB/2; s > 0; s >>= 1) {
        if (tid < s) redi[tid] = max(redi[tid], redi[tid + s]);
        __syncthreads();
    }
    const int W1max = redi[0]; __syncthreads();
    red[tid] = wn_mine; __syncthreads();
#pragma unroll
    for (int s = TPB/2; s > 0; s >>= 1) {
        if (tid < s) red[tid] = fminf(red[tid], red[tid + s]);
        __syncthreads();
    }
    const float wnmin = red[0]; __syncthreads();
    red[tid] = wn_mine; __syncthreads();
#pragma unroll
    for (int s = TPB/2; s > 0; s >>= 1) {
        if (tid < s) red[tid] = fmaxf(red[tid], red[tid + s]);
        __syncthreads();
    }
    const float wn_range = red[0] - wnmin;
    __syncthreads();

    // ================= main per-warp unit loop =================
    float lsum = 0.f;

    for (int u = bid + (tid >> 5) * GRID; u < NUNITS; u += USTRIDE) {
        const int vec = u * 32 + lane;
        const int b = vec >> 12, hw = vec & (HW - 1);
        const float* xb = in + ((size_t)b << 18) + hw;

        // ---- load x, stats, quantize (xv scoped: dead during scan) ----
        float sxmax = 0.f, X1 = 0.f, A = 0.f;
        int qx[16];
        {
            float xv[DIMD];
#pragma unroll
            for (int d = 0; d < DIMD; d++) {
                float t = xb[(size_t)d << 12];
                xv[d] = t;
                sxmax = fmaxf(sxmax, fabsf(t));
                X1 += fabsf(t);
                A = fmaf(t, t, A);
            }
            float inv_x = (sxmax > 0.f) ? 127.0f / sxmax : 0.f;
#pragma unroll
            for (int i = 0; i < 16; i++) {
                int q0 = __float2int_rn(xv[4*i+0] * inv_x);
                int q1 = __float2int_rn(xv[4*i+1] * inv_x);
                int q2 = __float2int_rn(xv[4*i+2] * inv_x);
                int q3 = __float2int_rn(xv[4*i+3] * inv_x);
                qx[i] = (q0 & 0xff) | ((q1 & 0xff) << 8)
                      | ((q2 & 0xff) << 16) | (q3 << 24);
            }
        }
        // rigorous integer margin: M = 1.02*(2*(0.5*Sum|qx| + 0.5*W1max + 16)
        //                               + wn_range/(2*sx*sw)) + 2
        int M;
        {
            const float sx = sxmax * (1.0f / 127.0f);
            const float sw = wmax * (1.0f / 127.0f);
            float mf = (sxmax > 0.f)
                ? 1.02f * ((float)W1max + 32.0f + X1 * (127.0f / sxmax)
                           + 0.5f * wn_range / (sx * sw))
                : 2.1e9f;
            mf = fminf(mf, 2.1e9f);
            M = (int)ceilf(mf) + 2;
        }

        // ---- int8 scan over 512 codes (4 independent dp4a chains) ----
        int smax = INT_MIN / 2, thr = INT_MIN / 2;
        int cnt = 0, ovf = 0;
        int candC[CAP], candS[CAP];
        const int4* qr = (const int4*)qw;
#pragma unroll 2
        for (int code = 0; code < NCODE; code++) {
            int4 v0 = qr[code*4+0], v1 = qr[code*4+1];
            int4 v2 = qr[code*4+2], v3 = qr[code*4+3];
            int a0 = __dp4a(v0.x, qx[0], 0);
            int a1 = __dp4a(v0.y, qx[1], 0);
            int a2 = __dp4a(v0.z, qx[2], 0);
            int a3 = __dp4a(v0.w, qx[3], 0);
            a0 = __dp4a(v1.x, qx[4],  a0); a1 = __dp4a(v1.y, qx[5],  a1);
            a2 = __dp4a(v1.z, qx[6],  a2); a3 = __dp4a(v1.w, qx[7],  a3);
            a0 = __dp4a(v2.x, qx[8],  a0); a1 = __dp4a(v2.y, qx[9],  a1);
            a2 = __dp4a(v2.z, qx[10], a2); a3 = __dp4a(v2.w, qx[11], a3);
            a0 = __dp4a(v3.x, qx[12], a0); a1 = __dp4a(v3.y, qx[13], a1);
            a2 = __dp4a(v3.z, qx[14], a2); a3 = __dp4a(v3.w, qx[15], a3);
            int s = (a0 + a1) + (a2 + a3);
            if (s > thr) {                       // rare path
                if (s > smax) { smax = s; thr = smax - M; }
                if (cnt == CAP) {                // purge entries below threshold
                    int nc = 0;
#pragma unroll
                    for (int sl = 0; sl < CAP; sl++)
                        if (candS[sl] > thr) { candS[nc] = candS[sl]; candC[nc] = candC[sl]; nc++; }
                    cnt = nc;
                }
                if (cnt < CAP) { candS[cnt] = s; candC[cnt] = code; cnt++; }
                else ovf = 1;                    // sticky -> exact full rescan
            }
        }

        // ---- exact rescore (R3-identical arithmetic), skipped when provable ----
        float xv[DIMD];
#pragma unroll
        for (int d = 0; d < DIMD; d++) xv[d] = xb[(size_t)d << 12];

        float bd = FLT_MAX; int bi = 0;
        if (ovf) {
            for (int code = 0; code < NCODE; code++) {
                float dv = exact_dist(xv, A, wp, wn_s, code);
                if (dv < bd) { bd = dv; bi = code; }
            }
        } else {
            const int fthr = smax - M;
            int live = 0;
#pragma unroll
            for (int sl = 0; sl < CAP; sl++)
                if (sl < cnt && candS[sl] >= fthr) live++;
            if (live == 1) {                     // unique candidate: argmin proven
#pragma unroll
                for (int sl = 0; sl < CAP; sl++)
                    if (sl < cnt && candS[sl] >= fthr) bi = candC[sl];
            } else {
                for (int e = 0; e < cnt; e++) {  // ascending codes: first-min ties
                    if (candS[e] >= fthr) {
                        float dv = exact_dist(xv, A, wp, wn_s, candC[e]);
                        if (dv < bd) { bd = dv; bi = candC[e]; }
                    }
                }
            }
        }

        // ---- epilogue ----
        out_disc[vec] = (float)bi;
        const float4* wb = (const float4*)(wp + bi * 68);
        float* qb = out_q + ((size_t)b << 18) + hw;
#pragma unroll
        for (int i = 0; i < 16; i++) {
            float4 wv = wb[i];
            float d0 = wv.x - xv[4*i+0];
            float d1 = wv.y - xv[4*i+1];
            float d2 = wv.z - xv[4*i+2];
            float d3 = wv.w - xv[4*i+3];
            qb[(size_t)(4*i+0) << 12] = xv[4*i+0] + d0;
            qb[(size_t)(4*i+1) << 12] = xv[4*i+1] + d1;
            qb[(size_t)(4*i+2) << 12] = xv[4*i+2] + d2;
            qb[(size_t)(4*i+3) << 12] = xv[4*i+3] + d3;
            lsum = fmaf(d0, d0, lsum); lsum = fmaf(d1, d1, lsum);
            lsum = fmaf(d2, d2, lsum); lsum = fmaf(d3, d3, lsum);
        }
    }

    // ---- deterministic loss: block partial, last block finalizes ----
    __syncthreads();
    red[tid] = lsum; __syncthreads();
#pragma unroll
    for (int s = TPB/2; s > 0; s >>= 1) {
        if (tid < s) red[tid] += red[tid + s];
        __syncthreads();
    }
    if (tid == 0) {
        g_psum[bid] = red[0];
        __threadfence();
        int arrived = atomicAdd(&g_ctr, 1);
        if (arrived == GRID - 1) {               // last block: sequential exact sum
            float s = 0.f;
            for (int i = 0; i < GRID; i++) s += g_psum[i];
            float m = s * inv_total;
            out_loss[0] = m + 0.25f * m;
            g_ctr = 0;                           // reset for next graph replay
            __threadfence();
        }
    }
}

extern "C" void kernel_launch(void* const* d_in, const int* in_sizes, int n_in,
                              void* d_out, int out_size)
{
    const float* in = (const float*)d_in[0];   // [32,64,64,64] fp32
    const float* w  = (const float*)d_in[1];   // [512,64] fp32
    const int n_elems = in_sizes[0];           // 8388608
    const int nvec    = n_elems / DIMD;        // 131072

    float* out      = (float*)d_out;
    float* out_disc = out;
    float* out_q    = out + nvec;
    float* out_loss = out + nvec + n_elems;

    static bool attr_set = false;
    if (!attr_set) {
        cudaFuncSetAttribute(vq_dp4a_kernel,
                             cudaFuncAttributeMaxDynamicSharedMemorySize, SMEM_TOTAL);
        attr_set = true;
    }
    vq_dp4a_kernel<<<GRID, TPB, SMEM_TOTAL>>>(in, w, out_disc, out_q,
                                              out_loss, 1.0f / (float)n_elems);
}